// round 16
// baseline (speedup 1.0000x reference)
#include <cuda_runtime.h>
#include <cuda_fp16.h>
#include <math.h>
#include <stdint.h>

#define DINLINE __device__ __forceinline__
typedef unsigned long long u64t;

// ---------------- scratch (device globals; no allocation allowed) -----------
__device__ __half g_yhd  [2048L * 16384];
__device__ __half g_y1   [2048L * 256];
__device__ __half g_qkv  [2048L * 768];
__device__ __half g_oattn[2048L * 256];
__device__ __half g_oproj[2048L * 256];
__device__ __half g_x2   [131072L * 256];
__device__ __half g_ln2  [131072L * 256];
__device__ __half g_h1   [131072L * 1024];
__device__ __half g_part [8L * 2048 * 256];
__device__ float  g_am   [16L * 8 * 1024];
__device__ float  g_al   [16L * 8 * 1024];
__device__ __half g_aa   [16L * 8 * 32 * 1024];
__device__ __half g_wdown[256L * 16384];
__device__ __half g_wup  [16384L * 256];
__device__ __half g_wqkv [768L * 256];
__device__ __half g_wproj[256L * 256];
__device__ __half g_wfc1 [1024L * 256];
__device__ __half g_wfc2 [256L * 1024];

// ---------------- packed f32x2 helpers ---------------------------------------
DINLINE u64t pack2(float lo, float hi) {
    u64t r; asm("mov.b64 %0, {%1, %2};" : "=l"(r) : "f"(lo), "f"(hi)); return r;
}
DINLINE void unpack2(u64t v, float& lo, float& hi) {
    asm("mov.b64 {%0, %1}, %2;" : "=f"(lo), "=f"(hi) : "l"(v));
}
DINLINE u64t fma2(u64t a, u64t b, u64t c) {
    u64t d; asm("fma.rn.f32x2 %0, %1, %2, %3;" : "=l"(d) : "l"(a), "l"(b), "l"(c)); return d;
}
DINLINE u64t mul2(u64t a, u64t b) {
    u64t d; asm("mul.rn.f32x2 %0, %1, %2;" : "=l"(d) : "l"(a), "l"(b)); return d;
}
DINLINE float gelu_fast(float v) {
    float u = v * (0.79788456080286536f + 0.0356774081363f * v * v);
    float th; asm("tanh.approx.f32 %0, %1;" : "=f"(th) : "f"(u));
    return 0.5f * v * (1.f + th);
}

// ---------------- fused weight convert (all 6 weights, one launch) -----------
__global__ void cvt_all_kernel(const float* __restrict__ s0, __half* d0, int n0,
                               const float* __restrict__ s1, __half* d1, int n1,
                               const float* __restrict__ s2, __half* d2, int n2,
                               const float* __restrict__ s3, __half* d3, int n3,
                               const float* __restrict__ s4, __half* d4, int n4,
                               const float* __restrict__ s5, __half* d5, int n5) {
    int i = blockIdx.x * 256 + threadIdx.x;
    int stride = gridDim.x * 256;
    int total = n0 + n1 + n2 + n3 + n4 + n5;
    for (; i < total; i += stride) {
        int j = i;
        if (j < n0) { d0[j] = __float2half_rn(s0[j]); continue; } j -= n0;
        if (j < n1) { d1[j] = __float2half_rn(s1[j]); continue; } j -= n1;
        if (j < n2) { d2[j] = __float2half_rn(s2[j]); continue; } j -= n2;
        if (j < n3) { d3[j] = __float2half_rn(s3[j]); continue; } j -= n3;
        if (j < n4) { d4[j] = __float2half_rn(s4[j]); continue; } j -= n4;
        d5[j] = __float2half_rn(s5[j]);
    }
}

// ---------------- LayerNorm (Tin = float or __half) ---------------------------
template <bool PERM, typename Tin>
__global__ void ln_kernel(const Tin* __restrict__ in,
                          const float* __restrict__ gamma,
                          const float* __restrict__ beta,
                          __half* __restrict__ out) {
    int row  = blockIdx.x * 8 + (threadIdx.x >> 5);
    int lane = threadIdx.x & 31;
    const Tin* p = in + (long)row * 256;

    float v[8];
    float s = 0.f;
#pragma unroll
    for (int i = 0; i < 8; i++) { v[i] = (float)p[lane + i * 32]; s += v[i]; }
#pragma unroll
    for (int o = 16; o > 0; o >>= 1) s += __shfl_xor_sync(0xffffffffu, s, o);
    float mean = s * (1.f / 256.f);
    float q = 0.f;
#pragma unroll
    for (int i = 0; i < 8; i++) { float d = v[i] - mean; q += d * d; }
#pragma unroll
    for (int o = 16; o > 0; o >>= 1) q += __shfl_xor_sync(0xffffffffu, q, o);
    float rstd = rsqrtf(q * (1.f / 256.f) + 1e-5f);

    long obase;
    if (PERM) {
        int b  = row >> 16;
        int hh = (row >> 8) & 255;
        int ww = row & 255;
        int r0 = hh >> 3, p0 = hh & 7;
        int r1 = ww >> 3, p1 = ww & 7;
        long n = (long)b * 1024 + r0 * 32 + r1;
        obase = n * 16384 + (long)(p0 * 8 + p1) * 256;
    } else {
        obase = (long)row * 256;
    }
#pragma unroll
    for (int i = 0; i < 8; i++) {
        int c = lane + i * 32;
        float y = (v[i] - mean) * rstd * gamma[c] + beta[c];
        out[obase + c] = __float2half_rn(y);
    }
}

// ---------------- NT fp16 GEMM, 128x128 tile (R13/R15 winner core) -------------
// BK=64, XOR-swizzled smem, 3-stage cp.async, 8 warps (2x4), warp tile 64x32,
// A-frag double-buffering, fp16 accum, 2 CTAs/SM.
// EPI: 0 bias->f16 | 1 bias+GELU->f16 | 2 bias+fold+fp32res -> f16 (x2)
//      | 4 raw fp16 partial (split-K over blockIdx.z; lossless)
template <int EPI>
__global__ void __launch_bounds__(256, 2)
gemm_nt(const __half* __restrict__ A,
        const __half* __restrict__ B,
        int M, int N, long K, int k_len,
        const float* __restrict__ bias,
        __half* __restrict__ outb,
        const float* __restrict__ res,
        __half* __restrict__ part) {
    constexpr int T_BYTES   = 128 * 128;
    constexpr int STG_BYTES = 2 * T_BYTES;

    extern __shared__ char sm[];
    const uint32_t sbase = (uint32_t)__cvta_generic_to_shared(sm);

    const int tid  = threadIdx.x;
    const int lane = tid & 31;
    const int wid  = tid >> 5;
    const int wm   = wid >> 2;
    const int wn   = wid & 3;
    const int m0   = blockIdx.y << 7;
    const int n0   = blockIdx.x << 7;
    const long koff = (long)blockIdx.z * k_len;
    const int nk   = k_len >> 6;

    auto ldAB = [&](int st, long kc) {
        uint32_t ab = sbase + st * STG_BYTES;
        uint32_t bb = ab + T_BYTES;
#pragma unroll
        for (int it = 0; it < 4; ++it) {
            int idx = tid + (it << 8);
            int r   = idx >> 3;
            int c8  = idx & 7;
            uint32_t dst = ab + (r << 7) + (((c8 ^ (r & 7))) << 4);
            const __half* src = A + (long)(m0 + r) * K + kc + (c8 << 3);
            asm volatile("cp.async.cg.shared.global [%0], [%1], 16;" ::"r"(dst), "l"(src));
        }
#pragma unroll
        for (int it = 0; it < 4; ++it) {
            int idx = tid + (it << 8);
            int r   = idx >> 3;
            int c8  = idx & 7;
            uint32_t dst = bb + (r << 7) + (((c8 ^ (r & 7))) << 4);
            const __half* src = B + (long)(n0 + r) * K + kc + (c8 << 3);
            asm volatile("cp.async.cg.shared.global [%0], [%1], 16;" ::"r"(dst), "l"(src));
        }
    };

    auto lda_addr = [&](uint32_t matbase, int rowbase, int kk) -> uint32_t {
        int r = rowbase + (lane & 15);
        int chunk = (kk >> 3) + (lane >> 4);
        return matbase + (r << 7) + ((chunk ^ (r & 7)) << 4);
    };

    ldAB(0, koff);
    asm volatile("cp.async.commit_group;");
    ldAB(1, koff + 64);
    asm volatile("cp.async.commit_group;");

    uint32_t acc[4][4] = {};
    uint32_t acc2[4][4] = {};
    uint32_t afA[2][4][4];

    for (int kt = 0; kt < nk; ++kt) {
        asm volatile("cp.async.wait_group 1;");
        __syncthreads();

        const int st = kt % 3;
        const uint32_t ab = sbase + st * STG_BYTES;
        const uint32_t bb = ab + T_BYTES;

#pragma unroll
        for (int mi = 0; mi < 4; mi++) {
            uint32_t addr = lda_addr(ab, wm * 64 + mi * 16, 0);
            asm volatile("ldmatrix.sync.aligned.m8n8.x4.shared.b16 {%0,%1,%2,%3}, [%4];"
                         : "=r"(afA[0][mi][0]), "=r"(afA[0][mi][1]),
                           "=r"(afA[0][mi][2]), "=r"(afA[0][mi][3])
                         : "r"(addr));
        }

#pragma unroll
        for (int kks = 0; kks < 4; ++kks) {
            const int kk  = kks << 4;
            const int cur = kks & 1;
            if (kks < 3) {
#pragma unroll
                for (int mi = 0; mi < 4; mi++) {
                    uint32_t addr = lda_addr(ab, wm * 64 + mi * 16, kk + 16);
                    asm volatile("ldmatrix.sync.aligned.m8n8.x4.shared.b16 {%0,%1,%2,%3}, [%4];"
                                 : "=r"(afA[cur ^ 1][mi][0]), "=r"(afA[cur ^ 1][mi][1]),
                                   "=r"(afA[cur ^ 1][mi][2]), "=r"(afA[cur ^ 1][mi][3])
                                 : "r"(addr));
                }
            }
            uint32_t bfr[4][2];
#pragma unroll
            for (int nj = 0; nj < 2; nj++) {
                uint32_t r0, r1, r2, r3;
                uint32_t addr = lda_addr(bb, wn * 32 + nj * 16, kk);
                asm volatile("ldmatrix.sync.aligned.m8n8.x4.shared.b16 {%0,%1,%2,%3}, [%4];"
                             : "=r"(r0), "=r"(r1), "=r"(r2), "=r"(r3)
                             : "r"(addr));
                bfr[2 * nj][0] = r0; bfr[2 * nj + 1][0] = r1;
                bfr[2 * nj][1] = r2; bfr[2 * nj + 1][1] = r3;
            }
#pragma unroll
            for (int mi = 0; mi < 4; mi++)
#pragma unroll
                for (int ni = 0; ni < 4; ni++) {
                    asm volatile(
                        "mma.sync.aligned.m16n8k16.row.col.f16.f16.f16.f16 "
                        "{%0,%1}, {%2,%3,%4,%5}, {%6,%7}, {%0,%1};"
                        : "+r"(acc[mi][ni]), "+r"(acc2[mi][ni])
                        : "r"(afA[cur][mi][0]), "r"(afA[cur][mi][1]),
                          "r"(afA[cur][mi][2]), "r"(afA[cur][mi][3]),
                          "r"(bfr[ni][0]), "r"(bfr[ni][1]));
                }
        }
        if (kt + 2 < nk) ldAB((kt + 2) % 3, koff + ((long)(kt + 2) << 6));
        asm volatile("cp.async.commit_group;");
    }

    // ---- epilogue ----
    const int rb = m0 + wm * 64;
    const int cb = n0 + wn * 32;
#pragma unroll
    for (int mi = 0; mi < 4; mi++)
#pragma unroll
        for (int ni = 0; ni < 4; ni++)
#pragma unroll
            for (int h = 0; h < 2; h++) {
                int row = rb + mi * 16 + (lane >> 2) + h * 8;
                int col = cb + ni * 8 + ((lane & 3) << 1);
                uint32_t ar = (h == 0) ? acc[mi][ni] : acc2[mi][ni];
                __half2 hv = *reinterpret_cast<__half2*>(&ar);
                if (EPI == 4) {
                    long idx = ((long)blockIdx.z * M + row) * N + col;
                    *reinterpret_cast<__half2*>(part + idx) = hv;
                    continue;
                }
                float v0 = __low2float(hv) + bias[col];
                float v1 = __high2float(hv) + bias[col + 1];
                if (EPI == 0) {
                    *reinterpret_cast<__half2*>(outb + (long)row * N + col) =
                        __floats2half2_rn(v0, v1);
                } else if (EPI == 1) {
                    *reinterpret_cast<__half2*>(outb + (long)row * N + col) =
                        __floats2half2_rn(gelu_fast(v0), gelu_fast(v1));
                } else {  // EPI 2: fold + fp32 residual -> f16
                    int b  = row >> 10;
                    int l  = row & 1023;
                    int r0 = l >> 5, r1 = l & 31;
                    int p  = col >> 8;
                    int c  = col & 255;
                    int p0 = p >> 3, p1 = p & 7;
                    int hh = (r0 << 3) | p0;
                    int ww = (r1 << 3) | p1;
                    long dst = ((((long)b * 256 + hh) * 256 + ww) * 256) + c;
                    *reinterpret_cast<__half2*>(outb + dst) =
                        __floats2half2_rn(res[dst] + v0, res[dst + 1] + v1);
                }
            }
}

// ---------------- fc2 wide GEMM: 64x256 tile (tail-friendly grid 2048) --------
// 2-stage (40 KB stages), 8 warps (2x4), warp tile 32x64, reads h1 ONCE.
__global__ void __launch_bounds__(256, 2)
gemm_fc2(const __half* __restrict__ A,      // h1 (M x 1024)
         const __half* __restrict__ B,      // wfc2 (256 x 1024)
         int M, long K,
         const float* __restrict__ bias,
         float* __restrict__ outf,
         const __half* __restrict__ resh) {
    constexpr int N = 256;
    constexpr int A_BYTES   = 64 * 128;           // 8 KB
    constexpr int B_BYTES   = 256 * 128;          // 32 KB
    constexpr int STG_BYTES = A_BYTES + B_BYTES;  // 40 KB

    extern __shared__ char sm[];
    const uint32_t sbase = (uint32_t)__cvta_generic_to_shared(sm);

    const int tid  = threadIdx.x;
    const int lane = tid & 31;
    const int wid  = tid >> 5;
    const int wm   = wid >> 2;                    // 0..1 (32-row bands)
    const int wn   = wid & 3;                     // 0..3 (64-col bands)
    const int m0   = blockIdx.y << 6;
    const int nk   = (int)(K >> 6);

    auto ldAB = [&](int st, long kc) {
        uint32_t ab = sbase + st * STG_BYTES;
        uint32_t bb = ab + A_BYTES;
#pragma unroll
        for (int it = 0; it < 2; ++it) {          // A: 512 16B vectors
            int idx = tid + (it << 8);
            int r   = idx >> 3;
            int c8  = idx & 7;
            uint32_t dst = ab + (r << 7) + (((c8 ^ (r & 7))) << 4);
            const __half* src = A + (long)(m0 + r) * K + kc + (c8 << 3);
            asm volatile("cp.async.cg.shared.global [%0], [%1], 16;" ::"r"(dst), "l"(src));
        }
#pragma unroll
        for (int it = 0; it < 8; ++it) {          // B: 2048 16B vectors
            int idx = tid + (it << 8);
            int r   = idx >> 3;
            int c8  = idx & 7;
            uint32_t dst = bb + (r << 7) + (((c8 ^ (r & 7))) << 4);
            const __half* src = B + (long)r * K + kc + (c8 << 3);
            asm volatile("cp.async.cg.shared.global [%0], [%1], 16;" ::"r"(dst), "l"(src));
        }
    };

    auto lda_addr = [&](uint32_t matbase, int rowbase, int kk) -> uint32_t {
        int r = rowbase + (lane & 15);
        int chunk = (kk >> 3) + (lane >> 4);
        return matbase + (r << 7) + ((chunk ^ (r & 7)) << 4);
    };

    ldAB(0, 0);
    asm volatile("cp.async.commit_group;");

    uint32_t acc[2][8][2] = {};

    for (int kt = 0; kt < nk; ++kt) {
        int cur = kt & 1;
        if (kt + 1 < nk) ldAB(cur ^ 1, (long)(kt + 1) << 6);
        asm volatile("cp.async.commit_group;");
        asm volatile("cp.async.wait_group 1;");
        __syncthreads();

        const uint32_t ab = sbase + cur * STG_BYTES;
        const uint32_t bb = ab + A_BYTES;

#pragma unroll
        for (int kks = 0; kks < 4; ++kks) {
            const int kk = kks << 4;
            uint32_t afA[2][4];
#pragma unroll
            for (int mi = 0; mi < 2; mi++) {
                uint32_t addr = lda_addr(ab, wm * 32 + mi * 16, kk);
                asm volatile("ldmatrix.sync.aligned.m8n8.x4.shared.b16 {%0,%1,%2,%3}, [%4];"
                             : "=r"(afA[mi][0]), "=r"(afA[mi][1]),
                               "=r"(afA[mi][2]), "=r"(afA[mi][3])
                             : "r"(addr));
            }
            uint32_t bfr[8][2];
#pragma unroll
            for (int nj = 0; nj < 4; nj++) {
                uint32_t r0, r1, r2, r3;
                uint32_t addr = lda_addr(bb, wn * 64 + nj * 16, kk);
                asm volatile("ldmatrix.sync.aligned.m8n8.x4.shared.b16 {%0,%1,%2,%3}, [%4];"
                             : "=r"(r0), "=r"(r1), "=r"(r2), "=r"(r3)
                             : "r"(addr));
                bfr[2 * nj][0] = r0; bfr[2 * nj + 1][0] = r1;
                bfr[2 * nj][1] = r2; bfr[2 * nj + 1][1] = r3;
            }
#pragma unroll
            for (int mi = 0; mi < 2; mi++)
#pragma unroll
                for (int ni = 0; ni < 8; ni++) {
                    asm volatile(
                        "mma.sync.aligned.m16n8k16.row.col.f16.f16.f16.f16 "
                        "{%0,%1}, {%2,%3,%4,%5}, {%6,%7}, {%0,%1};"
                        : "+r"(acc[mi][ni][0]), "+r"(acc[mi][ni][1])
                        : "r"(afA[mi][0]), "r"(afA[mi][1]),
                          "r"(afA[mi][2]), "r"(afA[mi][3]),
                          "r"(bfr[ni][0]), "r"(bfr[ni][1]));
                }
        }
        __syncthreads();
    }

    const int rb = m0 + wm * 32;
    const int cb = wn * 64;
#pragma unroll
    for (int mi = 0; mi < 2; mi++)
#pragma unroll
        for (int ni = 0; ni < 8; ni++)
#pragma unroll
            for (int h = 0; h < 2; h++) {
                int row = rb + mi * 16 + (lane >> 2) + h * 8;
                int col = cb + ni * 8 + ((lane & 3) << 1);
                __half2 hv = *reinterpret_cast<__half2*>(&acc[mi][ni][h]);
                long idx = (long)row * N + col;
                __half2 rr = *reinterpret_cast<const __half2*>(resh + idx);
                outf[idx]     = __low2float(rr)  + __low2float(hv)  + bias[col];
                outf[idx + 1] = __high2float(rr) + __high2float(hv) + bias[col + 1];
            }
}

// ---------------- down-proj split-K reduce (fp16 partials, fp32 sum) ----------
__global__ void reduce_down(const __half* __restrict__ part,
                            const float* __restrict__ bias,
                            __half* __restrict__ out) {
    int i = blockIdx.x * 256 + threadIdx.x;
    float s = bias[i & 255];
#pragma unroll
    for (int z = 0; z < 8; ++z) s += __half2float(part[(long)z * 524288 + i]);
    out[i] = __float2half_rn(s);
}

// ---------------- flash attention, split over key range (8 partials) ----------
__global__ void __launch_bounds__(128) attn_part_kernel(
    const __half* __restrict__ qkv,
    const float* __restrict__ rpe,
    float* __restrict__ am,
    float* __restrict__ al,
    __half* __restrict__ aa)
{
    const int bh = blockIdx.x;
    const int b  = bh >> 3;
    const int nh = bh & 7;
    const int js = blockIdx.z;
    const int t  = threadIdx.x;
    const int lq = blockIdx.y * 128 + t;
    const long rown = (long)b * 1024 + lq;

    u64t q2[16];
    {
        const __half* qp = qkv + rown * 768 + nh * 32;
#pragma unroll
        for (int d = 0; d < 16; d++) {
            float lo = __half2float(qp[2 * d])     * 0.1767766952966369f;
            float hi = __half2float(qp[2 * d + 1]) * 0.1767766952966369f;
            q2[d] = pack2(lo, hi);
        }
    }

    __shared__ float sk[128][32];
    __shared__ float sv[128][32];

#pragma unroll
    for (int it = 0; it < 16; ++it) {
        int idx = t + it * 128;
        int r = idx >> 4, d2 = idx & 15;
        long krow = (long)b * 1024 + js * 128 + r;
        __half2 kk = *(const __half2*)(qkv + krow * 768 + 256 + nh * 32 + 2 * d2);
        sk[r][2 * d2]     = __low2float(kk);
        sk[r][2 * d2 + 1] = __high2float(kk);
        __half2 vv = *(const __half2*)(qkv + krow * 768 + 512 + nh * 32 + 2 * d2);
        sv[r][2 * d2]     = __low2float(vv);
        sv[r][2 * d2 + 1] = __high2float(vv);
    }
    __syncthreads();

    float m = -1e30f, lsum = 0.f;
    u64t acc2[16];
#pragma unroll
    for (int d = 0; d < 16; d++) acc2[d] = 0ull;
    const int i0 = lq >> 5, i1 = lq & 31;

#pragma unroll 1
    for (int jc = 0; jc < 128; jc += 16) {
        float s[16];
        float cmax = -1e30f;
#pragma unroll
        for (int jj = 0; jj < 16; ++jj) {
            const u64t* kr = (const u64t*)sk[jc + jj];
            u64t s2 = 0ull;
#pragma unroll
            for (int d = 0; d < 16; ++d) s2 = fma2(q2[d], kr[d], s2);
            float lo, hi; unpack2(s2, lo, hi);
            int kl = js * 128 + jc + jj;
            int j0 = kl >> 5, j1 = kl & 31;
            float sc = lo + hi +
                __ldg(&rpe[((i0 - j0 + 31) * 63 + (i1 - j1 + 31)) * 8 + nh]);
            s[jj] = sc;
            cmax = fmaxf(cmax, sc);
        }
        float mnew  = fmaxf(m, cmax);
        float scale = __expf(m - mnew);
        lsum *= scale;
        u64t sc2 = pack2(scale, scale);
#pragma unroll
        for (int d = 0; d < 16; ++d) acc2[d] = mul2(acc2[d], sc2);
#pragma unroll
        for (int jj = 0; jj < 16; ++jj) {
            float p = __expf(s[jj] - mnew);
            lsum += p;
            u64t p2 = pack2(p, p);
            const u64t* vr = (const u64t*)sv[jc + jj];
#pragma unroll
            for (int d = 0; d < 16; ++d) acc2[d] = fma2(p2, vr[d], acc2[d]);
        }
        m = mnew;
    }

    const int zbase = bh * 8 + js;
    am[zbase * 1024 + lq] = m;
    al[zbase * 1024 + lq] = lsum;
    float inv = 1.f / lsum;
    __half* ap = aa + (long)zbase * 32768 + lq;
#pragma unroll
    for (int d = 0; d < 16; ++d) {
        float lo, hi; unpack2(acc2[d], lo, hi);
        ap[(2 * d) * 1024]     = __float2half_rn(lo * inv);
        ap[(2 * d + 1) * 1024] = __float2half_rn(hi * inv);
    }
}

__global__ void attn_combine_kernel(
    const float* __restrict__ am, const float* __restrict__ al,
    const __half* __restrict__ aa, __half* __restrict__ o)
{
    int idx = blockIdx.x * 256 + threadIdx.x;
    int bh = idx >> 10, lq = idx & 1023;
    int b = bh >> 3, nh = bh & 7;

    float mz[8];
    float M = -1e30f;
#pragma unroll
    for (int z = 0; z < 8; ++z) {
        mz[z] = am[(bh * 8 + z) * 1024 + lq];
        M = fmaxf(M, mz[z]);
    }
    float w[8];
    float L = 0.f;
#pragma unroll
    for (int z = 0; z < 8; ++z) {
        float lz = al[(bh * 8 + z) * 1024 + lq];
        w[z] = __expf(mz[z] - M) * lz;
        L += w[z];
    }
    float inv = 1.f / L;

    __half* op = o + ((long)b * 1024 + lq) * 256 + nh * 32;
#pragma unroll
    for (int d = 0; d < 32; d += 2) {
        float s0 = 0.f, s1 = 0.f;
#pragma unroll
        for (int z = 0; z < 8; ++z) {
            const __half* ap = aa + (long)(bh * 8 + z) * 32768 + lq;
            s0 += w[z] * __half2float(ap[d * 1024]);
            s1 += w[z] * __half2float(ap[(d + 1) * 1024]);
        }
        *(__half2*)(op + d) = __floats2half2_rn(s0 * inv, s1 * inv);
    }
}

// ----------------------------------------------------------------------------
extern "C" void kernel_launch(void* const* d_in, const int* in_sizes, int n_in,
                              void* d_out, int out_size) {
    const float* x      = (const float*)d_in[0];
    const float* ln1_g  = (const float*)d_in[1];
    const float* ln1_b  = (const float*)d_in[2];
    const float* ln2_g  = (const float*)d_in[3];
    const float* ln2_b  = (const float*)d_in[4];
    const float* rpe    = (const float*)d_in[5];
    const float* w_down = (const float*)d_in[6];
    const float* b_down = (const float*)d_in[7];
    const float* w_up   = (const float*)d_in[8];
    const float* b_up   = (const float*)d_in[9];
    const float* w_qkv  = (const float*)d_in[10];
    const float* b_qkv  = (const float*)d_in[11];
    const float* w_proj = (const float*)d_in[12];
    const float* b_proj = (const float*)d_in[13];
    const float* w_fc1  = (const float*)d_in[14];
    const float* b_fc1  = (const float*)d_in[15];
    const float* w_fc2  = (const float*)d_in[16];
    const float* b_fc2  = (const float*)d_in[17];
    float* out = (float*)d_out;

    void *p_yhd, *p_y1, *p_qkv, *p_oattn, *p_oproj, *p_x2, *p_ln2, *p_h1, *p_part;
    void *p_am, *p_al, *p_aa;
    void *p_wd, *p_wu, *p_wq, *p_wp, *p_w1, *p_w2;
    cudaGetSymbolAddress(&p_yhd,   g_yhd);
    cudaGetSymbolAddress(&p_y1,    g_y1);
    cudaGetSymbolAddress(&p_qkv,   g_qkv);
    cudaGetSymbolAddress(&p_oattn, g_oattn);
    cudaGetSymbolAddress(&p_oproj, g_oproj);
    cudaGetSymbolAddress(&p_x2,    g_x2);
    cudaGetSymbolAddress(&p_ln2,   g_ln2);
    cudaGetSymbolAddress(&p_h1,    g_h1);
    cudaGetSymbolAddress(&p_part,  g_part);
    cudaGetSymbolAddress(&p_am,    g_am);
    cudaGetSymbolAddress(&p_al,    g_al);
    cudaGetSymbolAddress(&p_aa,    g_aa);
    cudaGetSymbolAddress(&p_wd,    g_wdown);
    cudaGetSymbolAddress(&p_wu,    g_wup);
    cudaGetSymbolAddress(&p_wq,    g_wqkv);
    cudaGetSymbolAddress(&p_wp,    g_wproj);
    cudaGetSymbolAddress(&p_w1,    g_wfc1);
    cudaGetSymbolAddress(&p_w2,    g_wfc2);

    const int SMEM_GEMM = 3 * 32768;
    const int SMEM_FC2  = 2 * 40960;
    cudaFuncSetAttribute(gemm_nt<0>, cudaFuncAttributeMaxDynamicSharedMemorySize, SMEM_GEMM);
    cudaFuncSetAttribute(gemm_nt<1>, cudaFuncAttributeMaxDynamicSharedMemorySize, SMEM_GEMM);
    cudaFuncSetAttribute(gemm_nt<2>, cudaFuncAttributeMaxDynamicSharedMemorySize, SMEM_GEMM);
    cudaFuncSetAttribute(gemm_nt<4>, cudaFuncAttributeMaxDynamicSharedMemorySize, SMEM_GEMM);
    cudaFuncSetAttribute(gemm_fc2,   cudaFuncAttributeMaxDynamicSharedMemorySize, SMEM_FC2);

    cvt_all_kernel<<<592, 256>>>(
        w_down, (__half*)p_wd, 256 * 16384,
        w_up,   (__half*)p_wu, 16384 * 256,
        w_qkv,  (__half*)p_wq, 768 * 256,
        w_proj, (__half*)p_wp, 256 * 256,
        w_fc1,  (__half*)p_w1, 1024 * 256,
        w_fc2,  (__half*)p_w2, 256 * 1024);

    // LN1 fused with unfold permutation (reads fp32 x)
    ln_kernel<true, float><<<131072 / 8, 256>>>(x, ln1_g, ln1_b, (__half*)p_yhd);

    // down-proj split-K=8 -> fp16 partials, then reduce(+bias) -> f16
    gemm_nt<4><<<dim3(2, 16, 8), 256, SMEM_GEMM>>>(
        (const __half*)p_yhd, (const __half*)p_wd,
        2048, 256, 16384L, 2048, nullptr, nullptr, nullptr, (__half*)p_part);
    reduce_down<<<524288 / 256, 256>>>((const __half*)p_part, b_down, (__half*)p_y1);

    // qkv
    gemm_nt<0><<<dim3(6, 16), 256, SMEM_GEMM>>>(
        (const __half*)p_y1, (const __half*)p_wq,
        2048, 768, 256L, 256, b_qkv, (__half*)p_qkv, nullptr, nullptr);

    // attention: 8-way key-split partials + combine
    attn_part_kernel<<<dim3(16, 8, 8), 128>>>(
        (const __half*)p_qkv, rpe, (float*)p_am, (float*)p_al, (__half*)p_aa);
    attn_combine_kernel<<<16384 / 256, 256>>>(
        (const float*)p_am, (const float*)p_al, (const __half*)p_aa, (__half*)p_oattn);

    // proj
    gemm_nt<0><<<dim3(2, 16), 256, SMEM_GEMM>>>(
        (const __half*)p_oattn, (const __half*)p_wp,
        2048, 256, 256L, 256, b_proj, (__half*)p_oproj, nullptr, nullptr);

    // up-proj + fold + residual: x2(f16) = x(f32) + fold(...)
    gemm_nt<2><<<dim3(128, 16), 256, SMEM_GEMM>>>(
        (const __half*)p_oproj, (const __half*)p_wu,
        2048, 16384, 256L, 256, b_up, (__half*)p_x2, x, nullptr);

    // LN2 (reads f16 x2)
    ln_kernel<false, __half><<<131072 / 8, 256>>>((const __half*)p_x2, ln2_g, ln2_b,
                                                  (__half*)p_ln2);

    // fc1 + fast GELU
    gemm_nt<1><<<dim3(8, 1024), 256, SMEM_GEMM>>>(
        (const __half*)p_ln2, (const __half*)p_w1,
        131072, 1024, 256L, 256, b_fc1, (__half*)p_h1, nullptr, nullptr);

    // fc2 + residual -> out (fp32); 64-row tiles -> grid 2048 (tail-friendly)
    gemm_fc2<<<dim3(1, 2048), 256, SMEM_FC2>>>(
        (const __half*)p_h1, (const __half*)p_w2,
        131072, 1024L, b_fc2, out, (const __half*)p_x2);

    (void)in_sizes; (void)n_in; (void)out_size;
}

// round 17
// speedup vs baseline: 1.0204x; 1.0204x over previous
#include <cuda_runtime.h>
#include <cuda_fp16.h>
#include <math.h>
#include <stdint.h>

#define DINLINE __device__ __forceinline__
typedef unsigned long long u64t;

// ---------------- scratch (device globals; no allocation allowed) -----------
__device__ __half g_yhd  [2048L * 16384];
__device__ __half g_y1   [2048L * 256];
__device__ __half g_qkv  [2048L * 768];
__device__ __half g_oattn[2048L * 256];
__device__ __half g_oproj[2048L * 256];
__device__ __half g_x2   [131072L * 256];
__device__ __half g_ln2  [131072L * 256];
__device__ __half g_h1   [131072L * 1024];
__device__ __half g_part [8L * 2048 * 256];
__device__ float  g_am   [16L * 8 * 1024];
__device__ float  g_al   [16L * 8 * 1024];
__device__ __half g_aa   [16L * 8 * 1024 * 32];   // [z][lq][32] contiguous
__device__ __half g_wdown[256L * 16384];
__device__ __half g_wup  [16384L * 256];
__device__ __half g_wqkv [768L * 256];
__device__ __half g_wproj[256L * 256];
__device__ __half g_wfc1 [1024L * 256];
__device__ __half g_wfc2 [256L * 1024];

// ---------------- packed f32x2 helpers ---------------------------------------
DINLINE u64t pack2(float lo, float hi) {
    u64t r; asm("mov.b64 %0, {%1, %2};" : "=l"(r) : "f"(lo), "f"(hi)); return r;
}
DINLINE void unpack2(u64t v, float& lo, float& hi) {
    asm("mov.b64 {%0, %1}, %2;" : "=f"(lo), "=f"(hi) : "l"(v));
}
DINLINE u64t fma2(u64t a, u64t b, u64t c) {
    u64t d; asm("fma.rn.f32x2 %0, %1, %2, %3;" : "=l"(d) : "l"(a), "l"(b), "l"(c)); return d;
}
DINLINE u64t mul2(u64t a, u64t b) {
    u64t d; asm("mul.rn.f32x2 %0, %1, %2;" : "=l"(d) : "l"(a), "l"(b)); return d;
}
DINLINE float gelu_fast(float v) {
    float u = v * (0.79788456080286536f + 0.0356774081363f * v * v);
    float th; asm("tanh.approx.f32 %0, %1;" : "=f"(th) : "f"(u));
    return 0.5f * v * (1.f + th);
}

// ---------------- fused weight convert (all 6 weights, one launch) -----------
__global__ void cvt_all_kernel(const float* __restrict__ s0, __half* d0, int n0,
                               const float* __restrict__ s1, __half* d1, int n1,
                               const float* __restrict__ s2, __half* d2, int n2,
                               const float* __restrict__ s3, __half* d3, int n3,
                               const float* __restrict__ s4, __half* d4, int n4,
                               const float* __restrict__ s5, __half* d5, int n5) {
    int i = blockIdx.x * 256 + threadIdx.x;
    int stride = gridDim.x * 256;
    int total = n0 + n1 + n2 + n3 + n4 + n5;
    for (; i < total; i += stride) {
        int j = i;
        if (j < n0) { d0[j] = __float2half_rn(s0[j]); continue; } j -= n0;
        if (j < n1) { d1[j] = __float2half_rn(s1[j]); continue; } j -= n1;
        if (j < n2) { d2[j] = __float2half_rn(s2[j]); continue; } j -= n2;
        if (j < n3) { d3[j] = __float2half_rn(s3[j]); continue; } j -= n3;
        if (j < n4) { d4[j] = __float2half_rn(s4[j]); continue; } j -= n4;
        d5[j] = __float2half_rn(s5[j]);
    }
}

// ---------------- LayerNorm (Tin = float or __half) ---------------------------
template <bool PERM, typename Tin>
__global__ void ln_kernel(const Tin* __restrict__ in,
                          const float* __restrict__ gamma,
                          const float* __restrict__ beta,
                          __half* __restrict__ out) {
    int row  = blockIdx.x * 8 + (threadIdx.x >> 5);
    int lane = threadIdx.x & 31;
    const Tin* p = in + (long)row * 256;

    float v[8];
    float s = 0.f;
#pragma unroll
    for (int i = 0; i < 8; i++) { v[i] = (float)p[lane + i * 32]; s += v[i]; }
#pragma unroll
    for (int o = 16; o > 0; o >>= 1) s += __shfl_xor_sync(0xffffffffu, s, o);
    float mean = s * (1.f / 256.f);
    float q = 0.f;
#pragma unroll
    for (int i = 0; i < 8; i++) { float d = v[i] - mean; q += d * d; }
#pragma unroll
    for (int o = 16; o > 0; o >>= 1) q += __shfl_xor_sync(0xffffffffu, q, o);
    float rstd = rsqrtf(q * (1.f / 256.f) + 1e-5f);

    long obase;
    if (PERM) {
        int b  = row >> 16;
        int hh = (row >> 8) & 255;
        int ww = row & 255;
        int r0 = hh >> 3, p0 = hh & 7;
        int r1 = ww >> 3, p1 = ww & 7;
        long n = (long)b * 1024 + r0 * 32 + r1;
        obase = n * 16384 + (long)(p0 * 8 + p1) * 256;
    } else {
        obase = (long)row * 256;
    }
#pragma unroll
    for (int i = 0; i < 8; i++) {
        int c = lane + i * 32;
        float y = (v[i] - mean) * rstd * gamma[c] + beta[c];
        out[obase + c] = __float2half_rn(y);
    }
}

// ---------------- NT fp16 GEMM, 128x128 tile (R13/R15 winner core) -------------
// BK=64, XOR-swizzled smem, 3-stage cp.async, 8 warps (2x4), warp tile 64x32,
// A-frag double-buffering, fp16 accum, 2 CTAs/SM.
// EPI: 0 bias->f16 | 1 bias+GELU->f16 | 2 bias+fold+fp32res -> f16 (x2)
//      | 4 raw fp16 partial (split-K over blockIdx.z; lossless)
template <int EPI>
__global__ void __launch_bounds__(256, 2)
gemm_nt(const __half* __restrict__ A,
        const __half* __restrict__ B,
        int M, int N, long K, int k_len,
        const float* __restrict__ bias,
        __half* __restrict__ outb,
        const float* __restrict__ res,
        __half* __restrict__ part) {
    constexpr int T_BYTES   = 128 * 128;
    constexpr int STG_BYTES = 2 * T_BYTES;

    extern __shared__ char sm[];
    const uint32_t sbase = (uint32_t)__cvta_generic_to_shared(sm);

    const int tid  = threadIdx.x;
    const int lane = tid & 31;
    const int wid  = tid >> 5;
    const int wm   = wid >> 2;
    const int wn   = wid & 3;
    const int m0   = blockIdx.y << 7;
    const int n0   = blockIdx.x << 7;
    const long koff = (long)blockIdx.z * k_len;
    const int nk   = k_len >> 6;

    auto ldAB = [&](int st, long kc) {
        uint32_t ab = sbase + st * STG_BYTES;
        uint32_t bb = ab + T_BYTES;
#pragma unroll
        for (int it = 0; it < 4; ++it) {
            int idx = tid + (it << 8);
            int r   = idx >> 3;
            int c8  = idx & 7;
            uint32_t dst = ab + (r << 7) + (((c8 ^ (r & 7))) << 4);
            const __half* src = A + (long)(m0 + r) * K + kc + (c8 << 3);
            asm volatile("cp.async.cg.shared.global [%0], [%1], 16;" ::"r"(dst), "l"(src));
        }
#pragma unroll
        for (int it = 0; it < 4; ++it) {
            int idx = tid + (it << 8);
            int r   = idx >> 3;
            int c8  = idx & 7;
            uint32_t dst = bb + (r << 7) + (((c8 ^ (r & 7))) << 4);
            const __half* src = B + (long)(n0 + r) * K + kc + (c8 << 3);
            asm volatile("cp.async.cg.shared.global [%0], [%1], 16;" ::"r"(dst), "l"(src));
        }
    };

    auto lda_addr = [&](uint32_t matbase, int rowbase, int kk) -> uint32_t {
        int r = rowbase + (lane & 15);
        int chunk = (kk >> 3) + (lane >> 4);
        return matbase + (r << 7) + ((chunk ^ (r & 7)) << 4);
    };

    ldAB(0, koff);
    asm volatile("cp.async.commit_group;");
    ldAB(1, koff + 64);
    asm volatile("cp.async.commit_group;");

    uint32_t acc[4][4] = {};
    uint32_t acc2[4][4] = {};
    uint32_t afA[2][4][4];

    for (int kt = 0; kt < nk; ++kt) {
        asm volatile("cp.async.wait_group 1;");
        __syncthreads();

        const int st = kt % 3;
        const uint32_t ab = sbase + st * STG_BYTES;
        const uint32_t bb = ab + T_BYTES;

#pragma unroll
        for (int mi = 0; mi < 4; mi++) {
            uint32_t addr = lda_addr(ab, wm * 64 + mi * 16, 0);
            asm volatile("ldmatrix.sync.aligned.m8n8.x4.shared.b16 {%0,%1,%2,%3}, [%4];"
                         : "=r"(afA[0][mi][0]), "=r"(afA[0][mi][1]),
                           "=r"(afA[0][mi][2]), "=r"(afA[0][mi][3])
                         : "r"(addr));
        }

#pragma unroll
        for (int kks = 0; kks < 4; ++kks) {
            const int kk  = kks << 4;
            const int cur = kks & 1;
            if (kks < 3) {
#pragma unroll
                for (int mi = 0; mi < 4; mi++) {
                    uint32_t addr = lda_addr(ab, wm * 64 + mi * 16, kk + 16);
                    asm volatile("ldmatrix.sync.aligned.m8n8.x4.shared.b16 {%0,%1,%2,%3}, [%4];"
                                 : "=r"(afA[cur ^ 1][mi][0]), "=r"(afA[cur ^ 1][mi][1]),
                                   "=r"(afA[cur ^ 1][mi][2]), "=r"(afA[cur ^ 1][mi][3])
                                 : "r"(addr));
                }
            }
            uint32_t bfr[4][2];
#pragma unroll
            for (int nj = 0; nj < 2; nj++) {
                uint32_t r0, r1, r2, r3;
                uint32_t addr = lda_addr(bb, wn * 32 + nj * 16, kk);
                asm volatile("ldmatrix.sync.aligned.m8n8.x4.shared.b16 {%0,%1,%2,%3}, [%4];"
                             : "=r"(r0), "=r"(r1), "=r"(r2), "=r"(r3)
                             : "r"(addr));
                bfr[2 * nj][0] = r0; bfr[2 * nj + 1][0] = r1;
                bfr[2 * nj][1] = r2; bfr[2 * nj + 1][1] = r3;
            }
#pragma unroll
            for (int mi = 0; mi < 4; mi++)
#pragma unroll
                for (int ni = 0; ni < 4; ni++) {
                    asm volatile(
                        "mma.sync.aligned.m16n8k16.row.col.f16.f16.f16.f16 "
                        "{%0,%1}, {%2,%3,%4,%5}, {%6,%7}, {%0,%1};"
                        : "+r"(acc[mi][ni]), "+r"(acc2[mi][ni])
                        : "r"(afA[cur][mi][0]), "r"(afA[cur][mi][1]),
                          "r"(afA[cur][mi][2]), "r"(afA[cur][mi][3]),
                          "r"(bfr[ni][0]), "r"(bfr[ni][1]));
                }
        }
        if (kt + 2 < nk) ldAB((kt + 2) % 3, koff + ((long)(kt + 2) << 6));
        asm volatile("cp.async.commit_group;");
    }

    // ---- epilogue ----
    const int rb = m0 + wm * 64;
    const int cb = n0 + wn * 32;
#pragma unroll
    for (int mi = 0; mi < 4; mi++)
#pragma unroll
        for (int ni = 0; ni < 4; ni++)
#pragma unroll
            for (int h = 0; h < 2; h++) {
                int row = rb + mi * 16 + (lane >> 2) + h * 8;
                int col = cb + ni * 8 + ((lane & 3) << 1);
                uint32_t ar = (h == 0) ? acc[mi][ni] : acc2[mi][ni];
                __half2 hv = *reinterpret_cast<__half2*>(&ar);
                if (EPI == 4) {
                    long idx = ((long)blockIdx.z * M + row) * N + col;
                    *reinterpret_cast<__half2*>(part + idx) = hv;
                    continue;
                }
                float v0 = __low2float(hv) + bias[col];
                float v1 = __high2float(hv) + bias[col + 1];
                if (EPI == 0) {
                    *reinterpret_cast<__half2*>(outb + (long)row * N + col) =
                        __floats2half2_rn(v0, v1);
                } else if (EPI == 1) {
                    *reinterpret_cast<__half2*>(outb + (long)row * N + col) =
                        __floats2half2_rn(gelu_fast(v0), gelu_fast(v1));
                } else {  // EPI 2: fold + fp32 residual -> f16
                    int b  = row >> 10;
                    int l  = row & 1023;
                    int r0 = l >> 5, r1 = l & 31;
                    int p  = col >> 8;
                    int c  = col & 255;
                    int p0 = p >> 3, p1 = p & 7;
                    int hh = (r0 << 3) | p0;
                    int ww = (r1 << 3) | p1;
                    long dst = ((((long)b * 256 + hh) * 256 + ww) * 256) + c;
                    *reinterpret_cast<__half2*>(outb + dst) =
                        __floats2half2_rn(res[dst] + v0, res[dst + 1] + v1);
                }
            }
}

// ---------------- fc2 wide GEMM: 128x256 tile, reads h1 ONCE (R15 version) ----
__global__ void __launch_bounds__(256, 2)
gemm_fc2(const __half* __restrict__ A,      // h1 (M x 1024)
         const __half* __restrict__ B,      // wfc2 (256 x 1024)
         int M, long K,
         const float* __restrict__ bias,
         float* __restrict__ outf,
         const __half* __restrict__ resh) {
    constexpr int N = 256;
    constexpr int A_BYTES   = 128 * 128;
    constexpr int B_BYTES   = 256 * 128;
    constexpr int STG_BYTES = A_BYTES + B_BYTES;

    extern __shared__ char sm[];
    const uint32_t sbase = (uint32_t)__cvta_generic_to_shared(sm);

    const int tid  = threadIdx.x;
    const int lane = tid & 31;
    const int wid  = tid >> 5;
    const int wm   = wid >> 2;
    const int wn   = wid & 3;
    const int m0   = blockIdx.y << 7;
    const int nk   = (int)(K >> 6);

    auto ldAB = [&](int st, long kc) {
        uint32_t ab = sbase + st * STG_BYTES;
        uint32_t bb = ab + A_BYTES;
#pragma unroll
        for (int it = 0; it < 4; ++it) {
            int idx = tid + (it << 8);
            int r   = idx >> 3;
            int c8  = idx & 7;
            uint32_t dst = ab + (r << 7) + (((c8 ^ (r & 7))) << 4);
            const __half* src = A + (long)(m0 + r) * K + kc + (c8 << 3);
            asm volatile("cp.async.cg.shared.global [%0], [%1], 16;" ::"r"(dst), "l"(src));
        }
#pragma unroll
        for (int it = 0; it < 8; ++it) {
            int idx = tid + (it << 8);
            int r   = idx >> 3;
            int c8  = idx & 7;
            uint32_t dst = bb + (r << 7) + (((c8 ^ (r & 7))) << 4);
            const __half* src = B + (long)r * K + kc + (c8 << 3);
            asm volatile("cp.async.cg.shared.global [%0], [%1], 16;" ::"r"(dst), "l"(src));
        }
    };

    auto lda_addr = [&](uint32_t matbase, int rowbase, int kk) -> uint32_t {
        int r = rowbase + (lane & 15);
        int chunk = (kk >> 3) + (lane >> 4);
        return matbase + (r << 7) + ((chunk ^ (r & 7)) << 4);
    };

    ldAB(0, 0);
    asm volatile("cp.async.commit_group;");

    uint32_t acc[4][8][2] = {};

    for (int kt = 0; kt < nk; ++kt) {
        int cur = kt & 1;
        if (kt + 1 < nk) ldAB(cur ^ 1, (long)(kt + 1) << 6);
        asm volatile("cp.async.commit_group;");
        asm volatile("cp.async.wait_group 1;");
        __syncthreads();

        const uint32_t ab = sbase + cur * STG_BYTES;
        const uint32_t bb = ab + A_BYTES;

#pragma unroll
        for (int kks = 0; kks < 4; ++kks) {
            const int kk = kks << 4;
            uint32_t afA[4][4];
#pragma unroll
            for (int mi = 0; mi < 4; mi++) {
                uint32_t addr = lda_addr(ab, wm * 64 + mi * 16, kk);
                asm volatile("ldmatrix.sync.aligned.m8n8.x4.shared.b16 {%0,%1,%2,%3}, [%4];"
                             : "=r"(afA[mi][0]), "=r"(afA[mi][1]),
                               "=r"(afA[mi][2]), "=r"(afA[mi][3])
                             : "r"(addr));
            }
            uint32_t bfr[8][2];
#pragma unroll
            for (int nj = 0; nj < 4; nj++) {
                uint32_t r0, r1, r2, r3;
                uint32_t addr = lda_addr(bb, wn * 64 + nj * 16, kk);
                asm volatile("ldmatrix.sync.aligned.m8n8.x4.shared.b16 {%0,%1,%2,%3}, [%4];"
                             : "=r"(r0), "=r"(r1), "=r"(r2), "=r"(r3)
                             : "r"(addr));
                bfr[2 * nj][0] = r0; bfr[2 * nj + 1][0] = r1;
                bfr[2 * nj][1] = r2; bfr[2 * nj + 1][1] = r3;
            }
#pragma unroll
            for (int mi = 0; mi < 4; mi++)
#pragma unroll
                for (int ni = 0; ni < 8; ni++) {
                    asm volatile(
                        "mma.sync.aligned.m16n8k16.row.col.f16.f16.f16.f16 "
                        "{%0,%1}, {%2,%3,%4,%5}, {%6,%7}, {%0,%1};"
                        : "+r"(acc[mi][ni][0]), "+r"(acc[mi][ni][1])
                        : "r"(afA[mi][0]), "r"(afA[mi][1]),
                          "r"(afA[mi][2]), "r"(afA[mi][3]),
                          "r"(bfr[ni][0]), "r"(bfr[ni][1]));
                }
        }
        __syncthreads();
    }

    const int rb = m0 + wm * 64;
    const int cb = wn * 64;
#pragma unroll
    for (int mi = 0; mi < 4; mi++)
#pragma unroll
        for (int ni = 0; ni < 8; ni++)
#pragma unroll
            for (int h = 0; h < 2; h++) {
                int row = rb + mi * 16 + (lane >> 2) + h * 8;
                int col = cb + ni * 8 + ((lane & 3) << 1);
                __half2 hv = *reinterpret_cast<__half2*>(&acc[mi][ni][h]);
                long idx = (long)row * N + col;
                __half2 rr = *reinterpret_cast<const __half2*>(resh + idx);
                outf[idx]     = __low2float(rr)  + __low2float(hv)  + bias[col];
                outf[idx + 1] = __high2float(rr) + __high2float(hv) + bias[col + 1];
            }
}

// ---------------- down-proj split-K reduce (fp16 partials, fp32 sum) ----------
__global__ void reduce_down(const __half* __restrict__ part,
                            const float* __restrict__ bias,
                            __half* __restrict__ out) {
    int i = blockIdx.x * 256 + threadIdx.x;
    float s = bias[i & 255];
#pragma unroll
    for (int z = 0; z < 8; ++z) s += __half2float(part[(long)z * 524288 + i]);
    out[i] = __float2half_rn(s);
}

// ---------------- flash attention, split over key range (8 partials) ----------
// aa layout: [zbase][lq][32] -> fully coalesced uint4 stores/loads.
__global__ void __launch_bounds__(128) attn_part_kernel(
    const __half* __restrict__ qkv,
    const float* __restrict__ rpe,
    float* __restrict__ am,
    float* __restrict__ al,
    __half* __restrict__ aa)
{
    const int bh = blockIdx.x;
    const int b  = bh >> 3;
    const int nh = bh & 7;
    const int js = blockIdx.z;
    const int t  = threadIdx.x;
    const int lq = blockIdx.y * 128 + t;
    const long rown = (long)b * 1024 + lq;

    u64t q2[16];
    {
        const __half* qp = qkv + rown * 768 + nh * 32;
#pragma unroll
        for (int d = 0; d < 16; d++) {
            float lo = __half2float(qp[2 * d])     * 0.1767766952966369f;
            float hi = __half2float(qp[2 * d + 1]) * 0.1767766952966369f;
            q2[d] = pack2(lo, hi);
        }
    }

    __shared__ float sk[128][32];
    __shared__ float sv[128][32];

#pragma unroll
    for (int it = 0; it < 16; ++it) {
        int idx = t + it * 128;
        int r = idx >> 4, d2 = idx & 15;
        long krow = (long)b * 1024 + js * 128 + r;
        __half2 kk = *(const __half2*)(qkv + krow * 768 + 256 + nh * 32 + 2 * d2);
        sk[r][2 * d2]     = __low2float(kk);
        sk[r][2 * d2 + 1] = __high2float(kk);
        __half2 vv = *(const __half2*)(qkv + krow * 768 + 512 + nh * 32 + 2 * d2);
        sv[r][2 * d2]     = __low2float(vv);
        sv[r][2 * d2 + 1] = __high2float(vv);
    }
    __syncthreads();

    float m = -1e30f, lsum = 0.f;
    u64t acc2[16];
#pragma unroll
    for (int d = 0; d < 16; d++) acc2[d] = 0ull;
    const int i0 = lq >> 5, i1 = lq & 31;

#pragma unroll 1
    for (int jc = 0; jc < 128; jc += 16) {
        float s[16];
        float cmax = -1e30f;
#pragma unroll
        for (int jj = 0; jj < 16; ++jj) {
            const u64t* kr = (const u64t*)sk[jc + jj];
            u64t s2 = 0ull;
#pragma unroll
            for (int d = 0; d < 16; ++d) s2 = fma2(q2[d], kr[d], s2);
            float lo, hi; unpack2(s2, lo, hi);
            int kl = js * 128 + jc + jj;
            int j0 = kl >> 5, j1 = kl & 31;
            float sc = lo + hi +
                __ldg(&rpe[((i0 - j0 + 31) * 63 + (i1 - j1 + 31)) * 8 + nh]);
            s[jj] = sc;
            cmax = fmaxf(cmax, sc);
        }
        float mnew  = fmaxf(m, cmax);
        float scale = __expf(m - mnew);
        lsum *= scale;
        u64t sc2 = pack2(scale, scale);
#pragma unroll
        for (int d = 0; d < 16; ++d) acc2[d] = mul2(acc2[d], sc2);
#pragma unroll
        for (int jj = 0; jj < 16; ++jj) {
            float p = __expf(s[jj] - mnew);
            lsum += p;
            u64t p2 = pack2(p, p);
            const u64t* vr = (const u64t*)sv[jc + jj];
#pragma unroll
            for (int d = 0; d < 16; ++d) acc2[d] = fma2(p2, vr[d], acc2[d]);
        }
        m = mnew;
    }

    const int zbase = bh * 8 + js;
    am[zbase * 1024 + lq] = m;
    al[zbase * 1024 + lq] = lsum;
    float inv = 1.f / lsum;
    // contiguous per-thread 64B store: aa[(zbase*1024 + lq)*32 + d]
    __half hbuf[32];
#pragma unroll
    for (int d = 0; d < 16; ++d) {
        float lo, hi; unpack2(acc2[d], lo, hi);
        hbuf[2 * d]     = __float2half_rn(lo * inv);
        hbuf[2 * d + 1] = __float2half_rn(hi * inv);
    }
    uint4* dst = (uint4*)(aa + ((long)zbase * 1024 + lq) * 32);
    const uint4* srcb = (const uint4*)hbuf;
#pragma unroll
    for (int g = 0; g < 4; ++g) dst[g] = srcb[g];
}

__global__ void attn_combine_kernel(
    const float* __restrict__ am, const float* __restrict__ al,
    const __half* __restrict__ aa, __half* __restrict__ o)
{
    int idx = blockIdx.x * 256 + threadIdx.x;
    int bh = idx >> 10, lq = idx & 1023;
    int b = bh >> 3, nh = bh & 7;

    float mz[8];
    float M = -1e30f;
#pragma unroll
    for (int z = 0; z < 8; ++z) {
        mz[z] = am[(bh * 8 + z) * 1024 + lq];
        M = fmaxf(M, mz[z]);
    }
    float w[8];
    float L = 0.f;
#pragma unroll
    for (int z = 0; z < 8; ++z) {
        float lz = al[(bh * 8 + z) * 1024 + lq];
        w[z] = __expf(mz[z] - M) * lz;
        L += w[z];
    }
    float inv = 1.f / L;

    float acc[32];
#pragma unroll
    for (int d = 0; d < 32; ++d) acc[d] = 0.f;
#pragma unroll
    for (int z = 0; z < 8; ++z) {
        const uint4* ap = (const uint4*)(aa + ((long)(bh * 8 + z) * 1024 + lq) * 32);
        float wz = w[z];
#pragma unroll
        for (int g = 0; g < 4; ++g) {
            uint4 v = ap[g];
            const __half2* h2 = (const __half2*)&v;
#pragma unroll
            for (int k = 0; k < 4; ++k) {
                acc[g * 8 + 2 * k]     += wz * __low2float(h2[k]);
                acc[g * 8 + 2 * k + 1] += wz * __high2float(h2[k]);
            }
        }
    }

    __half* op = o + ((long)b * 1024 + lq) * 256 + nh * 32;
#pragma unroll
    for (int d = 0; d < 32; d += 2)
        *(__half2*)(op + d) = __floats2half2_rn(acc[d] * inv, acc[d + 1] * inv);
}

// ----------------------------------------------------------------------------
extern "C" void kernel_launch(void* const* d_in, const int* in_sizes, int n_in,
                              void* d_out, int out_size) {
    const float* x      = (const float*)d_in[0];
    const float* ln1_g  = (const float*)d_in[1];
    const float* ln1_b  = (const float*)d_in[2];
    const float* ln2_g  = (const float*)d_in[3];
    const float* ln2_b  = (const float*)d_in[4];
    const float* rpe    = (const float*)d_in[5];
    const float* w_down = (const float*)d_in[6];
    const float* b_down = (const float*)d_in[7];
    const float* w_up   = (const float*)d_in[8];
    const float* b_up   = (const float*)d_in[9];
    const float* w_qkv  = (const float*)d_in[10];
    const float* b_qkv  = (const float*)d_in[11];
    const float* w_proj = (const float*)d_in[12];
    const float* b_proj = (const float*)d_in[13];
    const float* w_fc1  = (const float*)d_in[14];
    const float* b_fc1  = (const float*)d_in[15];
    const float* w_fc2  = (const float*)d_in[16];
    const float* b_fc2  = (const float*)d_in[17];
    float* out = (float*)d_out;

    void *p_yhd, *p_y1, *p_qkv, *p_oattn, *p_oproj, *p_x2, *p_ln2, *p_h1, *p_part;
    void *p_am, *p_al, *p_aa;
    void *p_wd, *p_wu, *p_wq, *p_wp, *p_w1, *p_w2;
    cudaGetSymbolAddress(&p_yhd,   g_yhd);
    cudaGetSymbolAddress(&p_y1,    g_y1);
    cudaGetSymbolAddress(&p_qkv,   g_qkv);
    cudaGetSymbolAddress(&p_oattn, g_oattn);
    cudaGetSymbolAddress(&p_oproj, g_oproj);
    cudaGetSymbolAddress(&p_x2,    g_x2);
    cudaGetSymbolAddress(&p_ln2,   g_ln2);
    cudaGetSymbolAddress(&p_h1,    g_h1);
    cudaGetSymbolAddress(&p_part,  g_part);
    cudaGetSymbolAddress(&p_am,    g_am);
    cudaGetSymbolAddress(&p_al,    g_al);
    cudaGetSymbolAddress(&p_aa,    g_aa);
    cudaGetSymbolAddress(&p_wd,    g_wdown);
    cudaGetSymbolAddress(&p_wu,    g_wup);
    cudaGetSymbolAddress(&p_wq,    g_wqkv);
    cudaGetSymbolAddress(&p_wp,    g_wproj);
    cudaGetSymbolAddress(&p_w1,    g_wfc1);
    cudaGetSymbolAddress(&p_w2,    g_wfc2);

    const int SMEM_GEMM = 3 * 32768;
    const int SMEM_FC2  = 2 * 49152;
    cudaFuncSetAttribute(gemm_nt<0>, cudaFuncAttributeMaxDynamicSharedMemorySize, SMEM_GEMM);
    cudaFuncSetAttribute(gemm_nt<1>, cudaFuncAttributeMaxDynamicSharedMemorySize, SMEM_GEMM);
    cudaFuncSetAttribute(gemm_nt<2>, cudaFuncAttributeMaxDynamicSharedMemorySize, SMEM_GEMM);
    cudaFuncSetAttribute(gemm_nt<4>, cudaFuncAttributeMaxDynamicSharedMemorySize, SMEM_GEMM);
    cudaFuncSetAttribute(gemm_fc2,   cudaFuncAttributeMaxDynamicSharedMemorySize, SMEM_FC2);

    cvt_all_kernel<<<592, 256>>>(
        w_down, (__half*)p_wd, 256 * 16384,
        w_up,   (__half*)p_wu, 16384 * 256,
        w_qkv,  (__half*)p_wq, 768 * 256,
        w_proj, (__half*)p_wp, 256 * 256,
        w_fc1,  (__half*)p_w1, 1024 * 256,
        w_fc2,  (__half*)p_w2, 256 * 1024);

    // LN1 fused with unfold permutation (reads fp32 x)
    ln_kernel<true, float><<<131072 / 8, 256>>>(x, ln1_g, ln1_b, (__half*)p_yhd);

    // down-proj split-K=8 -> fp16 partials, then reduce(+bias) -> f16
    gemm_nt<4><<<dim3(2, 16, 8), 256, SMEM_GEMM>>>(
        (const __half*)p_yhd, (const __half*)p_wd,
        2048, 256, 16384L, 2048, nullptr, nullptr, nullptr, (__half*)p_part);
    reduce_down<<<524288 / 256, 256>>>((const __half*)p_part, b_down, (__half*)p_y1);

    // qkv
    gemm_nt<0><<<dim3(6, 16), 256, SMEM_GEMM>>>(
        (const __half*)p_y1, (const __half*)p_wq,
        2048, 768, 256L, 256, b_qkv, (__half*)p_qkv, nullptr, nullptr);

    // attention: 8-way key-split partials + combine (coalesced aa layout)
    attn_part_kernel<<<dim3(16, 8, 8), 128>>>(
        (const __half*)p_qkv, rpe, (float*)p_am, (float*)p_al, (__half*)p_aa);
    attn_combine_kernel<<<16384 / 256, 256>>>(
        (const float*)p_am, (const float*)p_al, (const __half*)p_aa, (__half*)p_oattn);

    // proj
    gemm_nt<0><<<dim3(2, 16), 256, SMEM_GEMM>>>(
        (const __half*)p_oattn, (const __half*)p_wp,
        2048, 256, 256L, 256, b_proj, (__half*)p_oproj, nullptr, nullptr);

    // up-proj + fold + residual: x2(f16) = x(f32) + fold(...)
    gemm_nt<2><<<dim3(128, 16), 256, SMEM_GEMM>>>(
        (const __half*)p_oproj, (const __half*)p_wu,
        2048, 16384, 256L, 256, b_up, (__half*)p_x2, x, nullptr);

    // LN2 (reads f16 x2)
    ln_kernel<false, __half><<<131072 / 8, 256>>>((const __half*)p_x2, ln2_g, ln2_b,
                                                  (__half*)p_ln2);

    // fc1 + fast GELU
    gemm_nt<1><<<dim3(8, 1024), 256, SMEM_GEMM>>>(
        (const __half*)p_ln2, (const __half*)p_w1,
        131072, 1024, 256L, 256, b_fc1, (__half*)p_h1, nullptr, nullptr);

    // fc2 + residual -> out (fp32); wide tile reads h1 ONCE
    gemm_fc2<<<dim3(1, 1024), 256, SMEM_FC2>>>(
        (const __half*)p_h1, (const __half*)p_w2,
        131072, 1024L, b_fc2, out, (const __half*)p_x2);

    (void)in_sizes; (void)n_in; (void)out_size;
}